// round 6
// baseline (speedup 1.0000x reference)
#include <cuda_runtime.h>
#include <cstdint>

// Fused embedding, round 6: gathers via LDG, stores via cp.async.bulk (TMA path).
//  - warp owns 32 consecutive rows = 8 stages of 4, double-buffered in SMEM
//  - per stage: 4 independent gather LDG.128 (branch-free select num_weight/cat),
//    numeric fixup (~10%), STS to stage buffer, fence.proxy.async, one
//    2KB cp.async.bulk.global.shared per stage (lane 0) -> store traffic
//    bypasses the L1tex wavefront queue and store scoreboards.

#define WARPS_PER_BLOCK 4
#define STAGE_ROWS 4            // rows per stage (2KB per bulk store)
#define STAGES 8                // 32 rows per warp

__device__ __forceinline__ uint32_t smem_u32(const void* p) {
    uint32_t a;
    asm("{ .reg .u64 t; cvta.to.shared.u64 t, %1; cvt.u32.u64 %0, t; }"
        : "=r"(a) : "l"(p));
    return a;
}

__global__ void __launch_bounds__(WARPS_PER_BLOCK * 32) emb_fused_kernel(
    const int*    __restrict__ fid,      // [B*L]
    const float*  __restrict__ fval,     // [B*L]
    const float4* __restrict__ cat,      // [N_CAT, 32] as float4
    const float4* __restrict__ w,        // [N_NUM, 32]
    const float4* __restrict__ b,        // [N_NUM, 32]
    const int*    __restrict__ to_num,   // [VOCAB+1]
    const int*    __restrict__ to_cat,   // [VOCAB+1]
    float4*       __restrict__ out)      // [B*L, 32]
{
    // [warp][buffer][row*32 + lane] : 4 warps * 2 * 4 rows * 512B = 16KB
    __shared__ __align__(16) float4 sbuf[WARPS_PER_BLOCK][2][STAGE_ROWS * 32];

    const int lane = threadIdx.x & 31;
    const int wid  = threadIdx.x >> 5;
    const int warp_global = blockIdx.x * WARPS_PER_BLOCK + wid;
    const int base = warp_global * 32;           // < 2^18, fits int

    // Per-lane scalar stage for row base+lane (coalesced; chain runs once, MLP=32)
    const int   id  = __ldg(&fid[base + lane]);
    const float v   = __ldg(&fval[base + lane]);
    const int  nidx = __ldg(&to_num[id]);
    const int  cidx = __ldg(&to_cat[id]);
    // packed: numeric -> (nidx-1) | signbit ; categorical -> cidx (>= 0)
    const int packed = (nidx > 0) ? ((nidx - 1) | 0x80000000) : cidx;

    #pragma unroll
    for (int s = 0; s < STAGES; s++) {
        const int buf = s & 1;
        float4 res[STAGE_ROWS];
        int    pp[STAGE_ROWS];

        // Gathers: branch-free src select, 4 independent LDG.128
        #pragma unroll
        for (int r = 0; r < STAGE_ROWS; r++) {
            const int p = __shfl_sync(0xffffffffu, packed, s * STAGE_ROWS + r);
            pp[r] = p;
            const int idx = ((p & 0x7fffffff) << 5) + lane;
            const float4* src = (p < 0) ? (w + idx) : (cat + idx);
            res[r] = __ldg(src);
        }

        // Numeric fixup (warp-uniform predicate, ~10% of rows)
        #pragma unroll
        for (int r = 0; r < STAGE_ROWS; r++) {
            if (pp[r] < 0) {
                const float vr = __shfl_sync(0xffffffffu, v, s * STAGE_ROWS + r);
                const float4 bv = __ldg(b + ((pp[r] & 0x7fffffff) << 5) + lane);
                res[r].x = fmaf(res[r].x, vr, bv.x);
                res[r].y = fmaf(res[r].y, vr, bv.y);
                res[r].z = fmaf(res[r].z, vr, bv.z);
                res[r].w = fmaf(res[r].w, vr, bv.w);
            }
        }

        // Ensure the bulk store that used this buffer (committed at stage s-2)
        // has completed before overwriting it.
        if (s >= 2) {
            if (lane == 0)
                asm volatile("cp.async.bulk.wait_group 1;" ::: "memory");
            __syncwarp();
        }

        // Stage rows into SMEM
        #pragma unroll
        for (int r = 0; r < STAGE_ROWS; r++)
            sbuf[wid][buf][r * 32 + lane] = res[r];

        // Order generic-proxy STS before async-proxy bulk read
        asm volatile("fence.proxy.async.shared::cta;" ::: "memory");
        __syncwarp();

        if (lane == 0) {
            const uint32_t src_s = smem_u32(&sbuf[wid][buf][0]);
            float4* dst = out + ((base + s * STAGE_ROWS) << 5);
            asm volatile(
                "cp.async.bulk.global.shared::cta.bulk_group [%0], [%1], %2;"
                :: "l"(dst), "r"(src_s), "n"(STAGE_ROWS * 512)
                : "memory");
            asm volatile("cp.async.bulk.commit_group;" ::: "memory");
        }
    }

    // Drain all pending bulk stores before exit.
    if (lane == 0)
        asm volatile("cp.async.bulk.wait_group 0;" ::: "memory");
}

// Tail kernel (safety for n_rows % 128 != 0; unused for B*L = 262144)
__global__ void __launch_bounds__(128) emb_tail_kernel(
    const int*    __restrict__ fid,
    const float*  __restrict__ fval,
    const float4* __restrict__ cat,
    const float4* __restrict__ w,
    const float4* __restrict__ b,
    const int*    __restrict__ to_num,
    const int*    __restrict__ to_cat,
    float4*       __restrict__ out,
    int start_row, int n_rows)
{
    int row  = start_row + blockIdx.x * (blockDim.x >> 5) + (threadIdx.x >> 5);
    int lane = threadIdx.x & 31;
    if (row >= n_rows) return;
    int id   = __ldg(&fid[row]);
    int nidx = __ldg(&to_num[id]);
    float4 r;
    if (nidx > 0) {
        float v = __ldg(&fval[row]);
        long  o = (long)(nidx - 1) * 32 + lane;
        float4 wv = __ldg(&w[o]);
        float4 bv = __ldg(&b[o]);
        r.x = fmaf(wv.x, v, bv.x);
        r.y = fmaf(wv.y, v, bv.y);
        r.z = fmaf(wv.z, v, bv.z);
        r.w = fmaf(wv.w, v, bv.w);
    } else {
        int c = __ldg(&to_cat[id]);
        r = __ldg(&cat[(long)c * 32 + lane]);
    }
    out[(long)row * 32 + lane] = r;
}

extern "C" void kernel_launch(void* const* d_in, const int* in_sizes, int n_in,
                              void* d_out, int out_size)
{
    const int*    fid    = (const int*)   d_in[0];
    const float*  fval   = (const float*) d_in[1];
    const float4* cat    = (const float4*)d_in[2];
    const float4* w      = (const float4*)d_in[3];
    const float4* b      = (const float4*)d_in[4];
    const int*    to_num = (const int*)   d_in[5];
    const int*    to_cat = (const int*)   d_in[6];
    float4*       out    = (float4*)      d_out;

    const int n_rows = in_sizes[0];                        // 262144
    const int rows_per_block = WARPS_PER_BLOCK * 32;       // 128
    const int full_blocks = n_rows / rows_per_block;       // 2048
    if (full_blocks > 0)
        emb_fused_kernel<<<full_blocks, WARPS_PER_BLOCK * 32>>>(
            fid, fval, cat, w, b, to_num, to_cat, out);
    const int done = full_blocks * rows_per_block;
    const int rem  = n_rows - done;
    if (rem > 0) {
        int tb = (rem + 3) / 4;
        emb_tail_kernel<<<tb, 128>>>(fid, fval, cat, w, b, to_num, to_cat, out, done, n_rows);
    }
}

// round 7
// speedup vs baseline: 1.1972x; 1.1972x over previous
#include <cuda_runtime.h>

// Fused embedding, round 7: R3 schedule + fine-grain wave balance + pairwise MLP.
//  - 64-thread blocks (2 warps) -> 4096 blocks: 27.7 blocks/SM, last-wave
//    imbalance ~3.7% instead of 7.4%
//  - warp owns 32 consecutive rows; rows processed in pairs with distinct
//    result registers (both gathers in flight before stores)
//  - packed shfl index (bit31 = numeric), int32 addressing, streaming stores

__global__ void __launch_bounds__(64) emb_fused_kernel(
    const int*    __restrict__ fid,      // [B*L]
    const float*  __restrict__ fval,     // [B*L]
    const float4* __restrict__ cat,      // [N_CAT, 32] as float4
    const float4* __restrict__ w,        // [N_NUM, 32]
    const float4* __restrict__ b,        // [N_NUM, 32]
    const int*    __restrict__ to_num,   // [VOCAB+1]
    const int*    __restrict__ to_cat,   // [VOCAB+1]
    float4*       __restrict__ out)      // [B*L, 32]
{
    const int lane = threadIdx.x & 31;
    const int warp_global = (blockIdx.x << 1) + (threadIdx.x >> 5);
    const int base = warp_global * 32;                 // < 2^18, fits int

    // Per-lane scalar stage for row base+lane (coalesced; chain runs once, MLP=32)
    const int   id  = __ldg(&fid[base + lane]);
    const float v   = __ldg(&fval[base + lane]);
    const int  nidx = __ldg(&to_num[id]);
    const int  cidx = __ldg(&to_cat[id]);

    // packed: numeric -> (nidx-1) | signbit ; categorical -> cidx (>= 0)
    const int packed = (nidx > 0) ? ((nidx - 1) | 0x80000000) : cidx;

    #pragma unroll
    for (int r = 0; r < 32; r += 2) {
        const int p0 = __shfl_sync(0xffffffffu, packed, r);
        const int p1 = __shfl_sync(0xffffffffu, packed, r + 1);

        // Both primary gathers issued back-to-back (branch-free address select)
        const int i0 = ((p0 & 0x7fffffff) << 5) + lane;
        const int i1 = ((p1 & 0x7fffffff) << 5) + lane;
        float4 r0 = (p0 < 0) ? __ldg(w + i0) : __ldg(cat + i0);
        float4 r1 = (p1 < 0) ? __ldg(w + i1) : __ldg(cat + i1);

        // Numeric fixup (warp-uniform predicates; ~10% of rows)
        if (p0 < 0) {
            const float vr = __shfl_sync(0xffffffffu, v, r);
            const float4 bv = __ldg(b + i0);
            r0.x = fmaf(r0.x, vr, bv.x);
            r0.y = fmaf(r0.y, vr, bv.y);
            r0.z = fmaf(r0.z, vr, bv.z);
            r0.w = fmaf(r0.w, vr, bv.w);
        }
        if (p1 < 0) {
            const float vr = __shfl_sync(0xffffffffu, v, r + 1);
            const float4 bv = __ldg(b + i1);
            r1.x = fmaf(r1.x, vr, bv.x);
            r1.y = fmaf(r1.y, vr, bv.y);
            r1.z = fmaf(r1.z, vr, bv.z);
            r1.w = fmaf(r1.w, vr, bv.w);
        }

        // Streaming stores (write-once output; don't pollute L2)
        __stcs(&out[((base + r)     << 5) + lane], r0);
        __stcs(&out[((base + r + 1) << 5) + lane], r1);
    }
}

// Tail kernel (safety for n_rows % 64 != 0; unused for B*L = 262144)
__global__ void __launch_bounds__(64) emb_tail_kernel(
    const int*    __restrict__ fid,
    const float*  __restrict__ fval,
    const float4* __restrict__ cat,
    const float4* __restrict__ w,
    const float4* __restrict__ b,
    const int*    __restrict__ to_num,
    const int*    __restrict__ to_cat,
    float4*       __restrict__ out,
    int start_row, int n_rows)
{
    int row  = start_row + blockIdx.x * (blockDim.x >> 5) + (threadIdx.x >> 5);
    int lane = threadIdx.x & 31;
    if (row >= n_rows) return;
    int id   = __ldg(&fid[row]);
    int nidx = __ldg(&to_num[id]);
    float4 r;
    if (nidx > 0) {
        float v = __ldg(&fval[row]);
        long  o = (long)(nidx - 1) * 32 + lane;
        float4 wv = __ldg(&w[o]);
        float4 bv = __ldg(&b[o]);
        r.x = fmaf(wv.x, v, bv.x);
        r.y = fmaf(wv.y, v, bv.y);
        r.z = fmaf(wv.z, v, bv.z);
        r.w = fmaf(wv.w, v, bv.w);
    } else {
        int c = __ldg(&to_cat[id]);
        r = __ldg(&cat[(long)c * 32 + lane]);
    }
    __stcs(&out[(long)row * 32 + lane], r);
}

extern "C" void kernel_launch(void* const* d_in, const int* in_sizes, int n_in,
                              void* d_out, int out_size)
{
    const int*    fid    = (const int*)   d_in[0];
    const float*  fval   = (const float*) d_in[1];
    const float4* cat    = (const float4*)d_in[2];
    const float4* w      = (const float4*)d_in[3];
    const float4* b      = (const float4*)d_in[4];
    const int*    to_num = (const int*)   d_in[5];
    const int*    to_cat = (const int*)   d_in[6];
    float4*       out    = (float4*)      d_out;

    const int n_rows = in_sizes[0];                 // 262144
    const int rows_per_block = 2 * 32;              // 2 warps x 32 rows
    const int full_blocks = n_rows / rows_per_block; // 4096
    if (full_blocks > 0)
        emb_fused_kernel<<<full_blocks, 64>>>(fid, fval, cat, w, b, to_num, to_cat, out);
    const int done = full_blocks * rows_per_block;
    const int rem  = n_rows - done;
    if (rem > 0) {
        int tb = (rem + 1) / 2;
        emb_tail_kernel<<<tb, 64>>>(fid, fval, cat, w, b, to_num, to_cat, out, done, n_rows);
    }
}